// round 6
// baseline (speedup 1.0000x reference)
#include <cuda_runtime.h>

// Problem constants
#define BB 8
#define CC 256
#define NN 65536              // 256*256 spatial
#define TILE 32               // pixels per tile
#define TPBATCH 2048          // tiles per batch
#define BPB 57                // blocks per batch (batch-aligned)
#define GRID_P (BB * BPB)     // 456 = 3 blocks/SM * 152 SMs (all resident)
#define TPB 36                // ceil(2048/57)
#define THREADS 256

// Output layout (flat float32 concat of reference returns)
#define OFF_LABELS  512
#define OFF_ONEHOT  (512 + BB * NN)              // 524800
#define OFF_CURDIST (OFF_ONEHOT + 2LL * BB * NN) // 1573376

// -------- device scratch (no allocations allowed) --------
__device__ float g_sums[3][BB * 2 * CC];   // per-iteration [b][k][c]
__device__ float g_counts[3][BB * 2];
__device__ float g_centers[2 * CC];
__device__ unsigned char g_labels[(long long)BB * NN];
__device__ float g_curdist;
__device__ unsigned g_arrive[3];

// -------- block reduce of 4 floats (256 threads) --------
__device__ __forceinline__ float4 blockReduce4(float4 v, float* scr) {
#pragma unroll
    for (int o = 16; o > 0; o >>= 1) {
        v.x += __shfl_down_sync(0xffffffffu, v.x, o);
        v.y += __shfl_down_sync(0xffffffffu, v.y, o);
        v.z += __shfl_down_sync(0xffffffffu, v.z, o);
        v.w += __shfl_down_sync(0xffffffffu, v.w, o);
    }
    int wid = threadIdx.x >> 5, lane = threadIdx.x & 31;
    __syncthreads();
    if (lane == 0) {
        scr[wid * 4 + 0] = v.x; scr[wid * 4 + 1] = v.y;
        scr[wid * 4 + 2] = v.z; scr[wid * 4 + 3] = v.w;
    }
    __syncthreads();
    if (threadIdx.x == 0) {
        float a = 0.f, b = 0.f, c = 0.f, d = 0.f;
#pragma unroll
        for (int w = 0; w < 8; w++) {
            a += scr[w * 4 + 0]; b += scr[w * 4 + 1];
            c += scr[w * 4 + 2]; d += scr[w * 4 + 3];
        }
        scr[0] = a; scr[1] = b; scr[2] = c; scr[3] = d;
    }
    __syncthreads();
    return make_float4(scr[0], scr[1], scr[2], scr[3]);
}

// -------- init: zero per-iteration scratch + sync counters --------
__global__ void k_init() {
    int tid = threadIdx.x;
#pragma unroll
    for (int it = 0; it < 3; it++) {
#pragma unroll
        for (int jj = 0; jj < 16; jj++) g_sums[it][jj * CC + tid] = 0.f;
        if (tid < 16) g_counts[it][tid] = 0.f;
        if (tid < 3) g_arrive[tid] = 0u;
    }
}

// -------- persistent: 3 x (assign + grid-sync + redundant update) --------
__global__ void __launch_bounds__(THREADS, 3) k_persist(
        const float* __restrict__ F, const float* __restrict__ cinit) {
    __shared__ float s_part[32 * 65];   // [g stride 65][j*8 + rot]
    __shared__ float s_cn[2 * CC];      // interleaved [c][k]
    __shared__ float s_labs[TILE];
    __shared__ float scr[32];
    __shared__ int s_cnt;

    const int tid = threadIdx.x;
    const int batch = blockIdx.x / BPB;
    const int bi = blockIdx.x % BPB;
    const int t0 = bi * TPB;
    int t1 = t0 + TPB; if (t1 > TPBATCH) t1 = TPBATCH;

    const int g = tid >> 3;   // channel group: channels c = g + 32k, k<8
    const int j = tid & 7;    // pixel quad: pixels 4j..4j+3

    // initial centers (redundant per block, identical)
    float co0 = cinit[tid], co1 = cinit[CC + tid];
    {
        float4 r = blockReduce4(make_float4(co0 * co0, co1 * co1, 0.f, 0.f), scr);
        float n0 = fmaxf(sqrtf(r.x), 1e-12f);
        float n1 = fmaxf(sqrtf(r.y), 1e-12f);
        s_cn[tid * 2 + 0] = co0 / n0;
        s_cn[tid * 2 + 1] = co1 / n1;
        if (tid == 0) s_cnt = 0;
    }
    __syncthreads();

    const float* Fb = F + (long long)batch * CC * NN + (long long)g * NN + 4 * j;
    const float2* cn2 = (const float2*)s_cn;
    const int poff = g * 65 + j * 8;

    for (int it = 0; it < 3; it++) {
        // ================= assign =================
        float acc1[8], accT[8];
#pragma unroll
        for (int k = 0; k < 8; k++) { acc1[k] = 0.f; accT[k] = 0.f; }
        int accCnt = 0;

        for (int t = t0; t < t1; t++) {
            const float* p = Fb + t * TILE;
            float4 v[8];
            float dp[8];
#pragma unroll
            for (int q = 0; q < 8; q++) dp[q] = 0.f;
#pragma unroll
            for (int k = 0; k < 8; k++) {
                v[k] = __ldcs((const float4*)(p + (long long)k * (32 * NN)));
                float2 w = cn2[g + 32 * k];
                dp[0] = fmaf(v[k].x, w.x, dp[0]); dp[1] = fmaf(v[k].x, w.y, dp[1]);
                dp[2] = fmaf(v[k].y, w.x, dp[2]); dp[3] = fmaf(v[k].y, w.y, dp[3]);
                dp[4] = fmaf(v[k].z, w.x, dp[4]); dp[5] = fmaf(v[k].z, w.y, dp[5]);
                dp[6] = fmaf(v[k].w, w.x, dp[6]); dp[7] = fmaf(v[k].w, w.y, dp[7]);
                accT[k] += (v[k].x + v[k].y) + (v[k].z + v[k].w);
            }
            if (tid == 0) { accCnt += s_cnt; s_cnt = 0; }
#pragma unroll
            for (int q = 0; q < 8; q++)
                s_part[poff + ((q + j) & 7)] = dp[q];
            __syncthreads();

            // labels: threads 0..63 = warps 0,1 (full warps)
            if (tid < 64) {
                const int pp = tid >> 1, kk = tid & 1;
                const int jj = pp >> 2, q = (pp & 3) * 2 + kk;
                const int col = jj * 8 + ((q + jj) & 7);
                float s = 0.f;
#pragma unroll
                for (int gg = 0; gg < 32; gg++) s += s_part[gg * 65 + col];
                float o = __shfl_xor_sync(0xffffffffu, s, 1);
                int lab = 0;
                if (!(tid & 1)) {
                    lab = (o > s) ? 1 : 0;   // argmin tie -> 0
                    s_labs[pp] = (float)lab;
                    g_labels[(long long)batch * NN + t * TILE + pp] = (unsigned char)lab;
                }
                unsigned bal = __ballot_sync(0xffffffffu, lab);
                if ((tid & 31) == 0) atomicAdd(&s_cnt, __popc(bal));
            }
            __syncthreads();

            // masked sums from registers
            float4 lb = *(const float4*)(s_labs + 4 * j);
#pragma unroll
            for (int k = 0; k < 8; k++) {
                float a = acc1[k];
                a = fmaf(lb.x, v[k].x, a); a = fmaf(lb.y, v[k].y, a);
                a = fmaf(lb.z, v[k].z, a); a = fmaf(lb.w, v[k].w, a);
                acc1[k] = a;
            }
        }
        __syncthreads();
        if (tid == 0) { accCnt += s_cnt; s_cnt = 0; }

        // flush: reduce across 8 j-lanes (contiguous in warp) + atomics
#pragma unroll
        for (int k = 0; k < 8; k++) {
            float a = acc1[k], s = accT[k];
#pragma unroll
            for (int o = 4; o > 0; o >>= 1) {
                a += __shfl_down_sync(0xffffffffu, a, o, 8);
                s += __shfl_down_sync(0xffffffffu, s, o, 8);
            }
            if (j == 0) {
                int c = g + 32 * k;
                atomicAdd(&g_sums[it][(batch * 2 + 1) * CC + c], a);
                atomicAdd(&g_sums[it][(batch * 2 + 0) * CC + c], s - a);
            }
        }
        if (tid == 0) {
            int npix = (t1 - t0) * TILE;
            atomicAdd(&g_counts[it][batch * 2 + 1], (float)accCnt);
            atomicAdd(&g_counts[it][batch * 2 + 0], (float)(npix - accCnt));
        }

        // ================= grid sync =================
        __threadfence();
        __syncthreads();
        if (tid == 0) {
            atomicAdd(&g_arrive[it], 1u);
            while (atomicAdd(&g_arrive[it], 0u) < (unsigned)GRID_P) __nanosleep(256);
        }
        __syncthreads();
        __threadfence();

        // ================= update (redundant per block, identical) =========
        float4 r = blockReduce4(make_float4(co0 * co0, co1 * co1, 0.f, 0.f), scr);
        float no0 = sqrtf(r.x), no1 = sqrtf(r.y);
        float nc0 = 0.f, nc1 = 0.f, cd = 0.f;
#pragma unroll
        for (int b = 0; b < BB; b++) {
            float cnt0 = g_counts[it][b * 2 + 0] + 1.0f;
            float cnt1 = g_counts[it][b * 2 + 1] + 1.0f;
            float ci0 = g_sums[it][(b * 2 + 0) * CC + tid] / cnt0;
            float ci1 = g_sums[it][(b * 2 + 1) * CC + tid] / cnt1;
            nc0 += ci0; nc1 += ci1;
            float4 q = blockReduce4(make_float4(ci0 * co0, ci0 * ci0, ci1 * co1, ci1 * ci1), scr);
            float den0 = fmaxf(sqrtf(q.y) * no0, 1e-8f);
            float den1 = fmaxf(sqrtf(q.w) * no1, 1e-8f);
            cd += 0.5f * (q.x / den0 + q.z / den1);
        }
        float cur = cd * 0.125f;
        nc0 *= 0.125f; nc1 *= 0.125f;
        float4 r2 = blockReduce4(make_float4(nc0 * nc0, nc1 * nc1, 0.f, 0.f), scr);
        float nn0 = fmaxf(sqrtf(r2.x), 1e-12f);
        float nn1 = fmaxf(sqrtf(r2.y), 1e-12f);
        s_cn[tid * 2 + 0] = nc0 / nn0;
        s_cn[tid * 2 + 1] = nc1 / nn1;
        g_centers[tid] = nc0; g_centers[CC + tid] = nc1;   // identical writes
        co0 = nc0; co1 = nc1;
        if (tid == 0) g_curdist = cur;                      // identical writes
        __syncthreads();   // s_cn ready before next assign

        if (cur < 0.01f) break;   // uniform across all blocks -> consistent
    }
}

// -------- finalize: write [centers | labels | onehot | cur_dist] --------
__global__ void k_final(float* __restrict__ out, long long outSize) {
    long long i = (long long)blockIdx.x * THREADS + threadIdx.x;
    if (i < 512 && i < outSize) out[i] = g_centers[i];
    if (i < (long long)BB * NN) {
        float lab = (float)g_labels[i];
        long long o1 = OFF_LABELS + i;
        long long o2 = OFF_ONEHOT + 2 * i;
        if (o1 < outSize) out[o1] = lab;
        if (o2 + 1 < outSize) {
            *(float2*)(out + o2) = make_float2(1.0f - lab, lab);
        }
    }
    if (i == 0 && OFF_CURDIST < outSize) out[OFF_CURDIST] = g_curdist;
}

extern "C" void kernel_launch(void* const* d_in, const int* in_sizes, int n_in,
                              void* d_out, int out_size) {
    const float* F = (const float*)d_in[0];
    const float* cinit = (const float*)d_in[1];
    if (n_in >= 2 && in_sizes[0] == 2 * CC) {  // tolerate swapped metadata order
        F = (const float*)d_in[1];
        cinit = (const float*)d_in[0];
    }
    k_init<<<1, THREADS>>>();
    k_persist<<<GRID_P, THREADS>>>(F, cinit);
    k_final<<<(BB * NN) / THREADS, THREADS>>>((float*)d_out, (long long)out_size);
}